// round 12
// baseline (speedup 1.0000x reference)
#include <cuda_runtime.h>
#include <cuda_bf16.h>
#include <cstdint>

// Problem constants
constexpr int D   = 128;
constexpr int M   = 8192;
constexpr int L   = 5;
constexpr int K   = 8;
constexpr int KL  = 4;
constexpr int G   = 4096;

constexpr int TILE = 128;
constexpr int PADM = M + K * TILE;    // 9216
constexpr int NTM  = PADM / TILE;     // 72
constexpr int PADG = G + KL * TILE;   // 4608
constexpr int NTG  = PADG / TILE;     // 36

// ---------------- device scratch (static; no allocation) ----------------
__device__ __align__(16) float g_hA[M * D];
__device__ __align__(16) float g_hB[M * D];

__device__ __align__(16) __nv_bfloat16 g_Y1hi[PADM * 512];
__device__ __align__(16) __nv_bfloat16 g_Y1lo[PADM * 512];
__device__ __align__(16) __nv_bfloat16 g_Y2hi[PADM * 256];
__device__ __align__(16) __nv_bfloat16 g_Y2lo[PADM * 256];

__device__ int g_perm   [L * PADM];
__device__ int g_tilefid[L * NTM];
__device__ int g_counts [L * K];
__device__ int g_cursor [L * K];
__device__ int g_offs   [L * K];

__device__ int g_permG   [PADG];
__device__ int g_tilefidG[NTG];
__device__ int g_countsG [KL];
__device__ int g_cursorG [KL];
__device__ int g_offsG   [KL];

__device__ int g_done;

// Weights transposed, layout [fid][n][Kd], separate hi/lo bf16
constexpr size_t OFF_W1  = 0;
constexpr size_t OFF_W2  = OFF_W1 + 8ull*512*256;
constexpr size_t OFF_W3  = OFF_W2 + 8ull*256*512;
constexpr size_t OFF_WL1 = OFF_W3 + 8ull*128*256;
constexpr size_t OFF_WL2 = OFF_WL1 + 4ull*512*256;
constexpr size_t WTOT    = OFF_WL2 + 4ull*128*512;
__device__ __align__(16) __nv_bfloat16 g_Whi[WTOT];
__device__ __align__(16) __nv_bfloat16 g_Wlo[WTOT];

// ---------------- PTX helpers ----------------
#define CPA16(dst, src) asm volatile("cp.async.cg.shared.global [%0], [%1], 16;" :: "r"(dst), "l"(src))
#define CPC()           asm volatile("cp.async.commit_group;" ::: "memory")
#define CPW1()          asm volatile("cp.async.wait_group 1;" ::: "memory")
#define LDSM4(r0, r1, r2, r3, a) \
    asm volatile("ldmatrix.sync.aligned.m8n8.x4.shared.b16 {%0,%1,%2,%3}, [%4];" \
        : "=r"(r0), "=r"(r1), "=r"(r2), "=r"(r3) : "r"(a))
#define MMA16816(acc, a0, a1, a2, a3, b0, b1) \
    asm volatile("mma.sync.aligned.m16n8k16.row.col.f32.bf16.bf16.f32 " \
        "{%0,%1,%2,%3}, {%4,%5,%6,%7}, {%8,%9}, {%0,%1,%2,%3};" \
        : "+f"((acc)[0]), "+f"((acc)[1]), "+f"((acc)[2]), "+f"((acc)[3]) \
        : "r"(a0), "r"(a1), "r"(a2), "r"(a3), "r"(b0), "r"(b1))

__device__ __forceinline__ uint32_t smem_u32(const void* p) {
    uint32_t a;
    asm("{ .reg .u64 t; cvta.to.shared.u64 t, %1; cvt.u32.u64 %0, t; }" : "=r"(a) : "l"(p));
    return a;
}

// ---------------- grouping kernels ----------------
__global__ void k_reset() {
    int t = blockIdx.x * blockDim.x + threadIdx.x;
    if (t == 0)       g_done = 0;
    if (t < L * PADM) g_perm[t] = -1;
    if (t < PADG)     g_permG[t] = -1;
    if (t < L * NTM)  g_tilefid[t] = -1;
    if (t < NTG)      g_tilefidG[t] = -1;
    if (t < L * K)    { g_counts[t] = 0; g_cursor[t] = 0; }
    if (t < KL)       { g_countsG[t] = 0; g_cursorG[t] = 0; }
}

// count + (last block) scan
__global__ void k_count(const int* __restrict__ nf, const int* __restrict__ lf) {
    int t = blockIdx.x * blockDim.x + threadIdx.x;
    if (t < L * M) {
        int l = t / M;
        atomicAdd(&g_counts[l * K + nf[t]], 1);
    } else if (t < L * M + G) {
        atomicAdd(&g_countsG[lf[t - L * M]], 1);
    }
    __threadfence();
    __syncthreads();
    __shared__ int isLast;
    if (threadIdx.x == 0) {
        int ticket = atomicAdd(&g_done, 1);
        isLast = (ticket == (int)gridDim.x - 1) ? 1 : 0;
    }
    __syncthreads();
    if (isLast) {
        __threadfence();
        int i = threadIdx.x;
        if (i < L) {
            int l = i, off = 0;
            for (int k = 0; k < K; k++) {
                g_offs[l * K + k] = off;
                int nt = (g_counts[l * K + k] + TILE - 1) / TILE;
                for (int tt = 0; tt < nt; tt++) g_tilefid[l * NTM + off / TILE + tt] = k;
                off += nt * TILE;
            }
        } else if (i == L) {
            int off = 0;
            for (int k = 0; k < KL; k++) {
                g_offsG[k] = off;
                int nt = (g_countsG[k] + TILE - 1) / TILE;
                for (int tt = 0; tt < nt; tt++) g_tilefidG[off / TILE + tt] = k;
                off += nt * TILE;
            }
        }
    }
}

constexpr int SCAT_BLOCKS = (L * M + G + 255) / 256;   // 176
__global__ void k_scatter_wconv(const int* __restrict__ nf, const int* __restrict__ lf,
                                const float* __restrict__ W1, const float* __restrict__ W2,
                                const float* __restrict__ W3, const float* __restrict__ Wl1,
                                const float* __restrict__ Wl2) {
    if (blockIdx.x < SCAT_BLOCKS) {
        int t = blockIdx.x * blockDim.x + threadIdx.x;
        if (t < L * M) {
            int l = t / M, m = t % M;
            int f = nf[t];
            int pos = g_offs[l * K + f] + atomicAdd(&g_cursor[l * K + f], 1);
            g_perm[l * PADM + pos] = m;
        } else if (t < L * M + G) {
            int s = t - L * M;
            int f = lf[s];
            int pos = g_offsG[f] + atomicAdd(&g_cursorG[f], 1);
            g_permG[pos] = s;
        }
        return;
    }
    __shared__ float ts[32][33];
    int tix = blockIdx.x - SCAT_BLOCKS;
    const float* W; size_t woff; int Kd, Nd;
    if (tix < 1024)      { W = W1;  woff = OFF_W1;  Kd = 256; Nd = 512; }
    else if (tix < 2048) { W = W2;  woff = OFF_W2;  Kd = 512; Nd = 256; tix -= 1024; }
    else if (tix < 2304) { W = W3;  woff = OFF_W3;  Kd = 256; Nd = 128; tix -= 2048; }
    else if (tix < 2816) { W = Wl1; woff = OFF_WL1; Kd = 256; Nd = 512; tix -= 2304; }
    else                 { W = Wl2; woff = OFF_WL2; Kd = 512; Nd = 128; tix -= 2816; }
    int ntk = Kd / 32;
    int per = ntk * (Nd / 32);
    int f = tix / per, rem = tix % per;
    int n0 = (rem / ntk) * 32, k0 = (rem % ntk) * 32;
    int tx = threadIdx.x & 31, ty = threadIdx.x >> 5;

    const float* Wf = W + (size_t)f * Kd * Nd;
    for (int rr = ty; rr < 32; rr += 8)
        ts[rr][tx] = Wf[(size_t)(k0 + rr) * Nd + n0 + tx];
    __syncthreads();
    for (int rr = ty; rr < 32; rr += 8) {
        float x = ts[tx][rr];
        __nv_bfloat16 h = __float2bfloat16(x);
        __nv_bfloat16 l = __float2bfloat16(x - __bfloat162float(h));
        size_t o = woff + (size_t)f * Nd * Kd + (size_t)(n0 + rr) * Kd + k0 + tx;
        g_Whi[o] = h;
        g_Wlo[o] = l;
    }
}

// ---------------- GEMM geometry: BN=64, 2 stages ----------------
constexpr int SST = 40;                        // halves per smem row
constexpr int BN  = 64;
constexpr int OFF_AL = 128 * SST;
constexpr int OFF_BH = 256 * SST;
constexpr int OFF_BL = 256 * SST + BN * SST;
constexpr int STAGEH = (256 + 2 * BN) * SST;   // 15360 halves
constexpr int GEMM_SMEM = 2 * STAGEH * 2;      // 61440 B -> 3 CTAs/SM

// compute one 16-wide K slice. Warp tile 32x32 (warp grid 4m x 2n).
// 3 products; B fragments loaded once per product pair; A-hi kept live.
__device__ __forceinline__ void compute_kk(
    uint32_t s0, int wmBase, int wnBase, int lrow, int lcol, int kk, float (*acc)[4][4])
{
    uint32_t ah[2][4], al[2][4];
#pragma unroll
    for (int mt = 0; mt < 2; mt++) {
        uint32_t ad = s0 + (uint32_t)((wmBase + mt * 16 + lrow) * SST + kk + lcol) * 2;
        LDSM4(ah[mt][0], ah[mt][1], ah[mt][2], ah[mt][3], ad);
        LDSM4(al[mt][0], al[mt][1], al[mt][2], al[mt][3], ad + OFF_AL * 2);
    }
    uint32_t bb[4][2];
#pragma unroll
    for (int p = 0; p < 2; p++) {
        uint32_t r0, r1, r2, r3;
        uint32_t ad = s0 + (uint32_t)(OFF_BH + (wnBase + p * 16 + lrow) * SST + kk + lcol) * 2;
        LDSM4(r0, r1, r2, r3, ad);
        bb[2 * p][0] = r0; bb[2 * p + 1][0] = r1;
        bb[2 * p][1] = r2; bb[2 * p + 1][1] = r3;
    }
#pragma unroll
    for (int mt = 0; mt < 2; mt++)
#pragma unroll
        for (int nt = 0; nt < 4; nt++)
            MMA16816(acc[mt][nt], ah[mt][0], ah[mt][1], ah[mt][2], ah[mt][3], bb[nt][0], bb[nt][1]);
#pragma unroll
    for (int mt = 0; mt < 2; mt++)
#pragma unroll
        for (int nt = 0; nt < 4; nt++)
            MMA16816(acc[mt][nt], al[mt][0], al[mt][1], al[mt][2], al[mt][3], bb[nt][0], bb[nt][1]);
#pragma unroll
    for (int p = 0; p < 2; p++) {
        uint32_t r0, r1, r2, r3;
        uint32_t ad = s0 + (uint32_t)(OFF_BL + (wnBase + p * 16 + lrow) * SST + kk + lcol) * 2;
        LDSM4(r0, r1, r2, r3, ad);
        bb[2 * p][0] = r0; bb[2 * p + 1][0] = r1;
        bb[2 * p][1] = r2; bb[2 * p + 1][1] = r3;
    }
#pragma unroll
    for (int mt = 0; mt < 2; mt++)
#pragma unroll
        for (int nt = 0; nt < 4; nt++)
            MMA16816(acc[mt][nt], ah[mt][0], ah[mt][1], ah[mt][2], ah[mt][3], bb[nt][0], bb[nt][1]);
}

// ============ fused gather + GEMM1 ============
__global__ __launch_bounds__(256, 3) void k_gemm_fused(
    int lv, const int* __restrict__ li, const int* __restrict__ ri,
    int hsel, const float* __restrict__ emb, const int* __restrict__ lmap,
    size_t woff, const float* __restrict__ bias_base)
{
    const int fid = (lv < L) ? g_tilefid[lv * NTM + blockIdx.x] : g_tilefidG[blockIdx.x];
    if (fid < 0) return;

    constexpr int Kd = 256, Nd = 512;
    constexpr int NC = Kd / 32;                // 8

    const float* hsrc = (hsel == 0) ? emb : ((hsel == 3) ? g_hA : g_hB);
    const __nv_bfloat16* __restrict__ Bhi = g_Whi + woff + (size_t)fid * Nd * Kd;
    const __nv_bfloat16* __restrict__ Blo = g_Wlo + woff + (size_t)fid * Nd * Kd;
    const float* __restrict__ bias = bias_base + (size_t)fid * Nd;

    const int rowBase = blockIdx.x * 128;
    const int colBase = blockIdx.y * BN;
    const int tid = threadIdx.x, lane = tid & 31, wid = tid >> 5;
    const int wmBase = (wid & 3) * 32;
    const int wnBase = (wid >> 2) * 32;
    const int gq = lane >> 2, tq = lane & 3;
    const int lrow = lane & 15, lcol = (lane >> 4) << 3;

    extern __shared__ __align__(16) unsigned short smem[];
    const uint32_t saddr = smem_u32(smem);

    float acc[2][4][4];
#pragma unroll
    for (int a = 0; a < 2; a++)
#pragma unroll
        for (int b = 0; b < 4; b++)
#pragma unroll
            for (int c = 0; c < 4; c++) acc[a][b][c] = 0.f;

    const int lr = tid >> 1, lp = tid & 1;
    const int* perm = (lv < L) ? (g_perm + lv * PADM) : g_permG;
    const int node = perm[rowBase + lr];
    const float* pL = nullptr;
    const float* pR = nullptr;
    if (node >= 0) {
        int il = li[node], ir = ri[node];
        if (lmap) { il = lmap[il]; ir = lmap[ir]; }
        pL = hsrc + (size_t)il * 128 + lp * 16;
        pR = hsrc + (size_t)ir * 128 + lp * 16;
    }

    float4 pa[4];
    auto ldA = [&](int c) {
        if (node >= 0) {
            const float* base = ((c < 4) ? pL : pR) + (c & 3) * 32;
#pragma unroll
            for (int j = 0; j < 4; j++) pa[j] = *(const float4*)(base + 4 * j);
        } else {
#pragma unroll
            for (int j = 0; j < 4; j++) pa[j] = make_float4(0.f, 0.f, 0.f, 0.f);
        }
    };
    auto stsA = [&](int st) {
        __align__(16) __nv_bfloat16 hi16[16], lo16[16];
        const float* v = (const float*)pa;
#pragma unroll
        for (int i = 0; i < 16; i++) {
            __nv_bfloat16 h = __float2bfloat16(v[i]);
            hi16[i] = h;
            lo16[i] = __float2bfloat16(v[i] - __bfloat162float(h));
        }
        unsigned short* dh = smem + st * STAGEH + lr * SST + lp * 16;
        *(uint4*)(dh)              = *(uint4*)&hi16[0];
        *(uint4*)(dh + 8)          = *(uint4*)&hi16[8];
        *(uint4*)(dh + OFF_AL)     = *(uint4*)&lo16[0];
        *(uint4*)(dh + OFF_AL + 8) = *(uint4*)&lo16[8];
    };
    auto issueB = [&](int c, int st) {
        if (lr < BN) {
            int k0 = c * 32;
            uint32_t dst = saddr + (uint32_t)(st * STAGEH + lr * SST + lp * 16) * 2;
            const __nv_bfloat16* bh = Bhi + (size_t)(colBase + lr) * Kd + k0 + lp * 16;
            const __nv_bfloat16* bl = Blo + (size_t)(colBase + lr) * Kd + k0 + lp * 16;
            CPA16(dst + OFF_BH * 2, bh);    CPA16(dst + OFF_BH * 2 + 16, bh + 8);
            CPA16(dst + OFF_BL * 2, bl);    CPA16(dst + OFF_BL * 2 + 16, bl + 8);
        }
    };

    // prologue: A0 in smem, A1 in regs, B0/B1 in flight
    ldA(0); stsA(0);
    ldA(1);
    issueB(0, 0); CPC();
    issueB(1, 1); CPC();

    for (int c = 0; c < NC; c++) {
        const int st = c & 1;
        CPW1();                       // B stage st complete
        __syncthreads();
        if (c + 1 < NC) stsA(st ^ 1); // write A for next stage (its compute finished last iter)
        if (c + 2 < NC) ldA(c + 2);

        const uint32_t s0 = saddr + (uint32_t)(st * STAGEH) * 2;
        compute_kk(s0, wmBase, wnBase, lrow, lcol, 0,  acc);
        compute_kk(s0, wmBase, wnBase, lrow, lcol, 16, acc);

        __syncthreads();
        if (c + 2 < NC) issueB(c + 2, st);
        CPC();
    }

    // epilogue: relu, split hi/lo -> Y1
#pragma unroll
    for (int mt = 0; mt < 2; mt++) {
#pragma unroll
        for (int hr = 0; hr < 2; hr++) {
            int row = rowBase + wmBase + mt * 16 + hr * 8 + gq;
#pragma unroll
            for (int nt = 0; nt < 4; nt++) {
                int col = colBase + wnBase + nt * 8 + 2 * tq;
                float vx = fmaxf(acc[mt][nt][hr * 2 + 0] + bias[col], 0.f);
                float vy = fmaxf(acc[mt][nt][hr * 2 + 1] + bias[col + 1], 0.f);
                __nv_bfloat16 hx = __float2bfloat16(vx);
                __nv_bfloat16 hy = __float2bfloat16(vy);
                __nv_bfloat16 lx = __float2bfloat16(vx - __bfloat162float(hx));
                __nv_bfloat16 ly = __float2bfloat16(vy - __bfloat162float(hy));
                uint32_t hp  = ((uint32_t)__bfloat16_as_ushort(hy) << 16) | __bfloat16_as_ushort(hx);
                uint32_t lp2 = ((uint32_t)__bfloat16_as_ushort(ly) << 16) | __bfloat16_as_ushort(lx);
                size_t o = (size_t)row * Nd + col;
                *(uint32_t*)&g_Y1hi[o] = hp;
                *(uint32_t*)&g_Y1lo[o] = lp2;
            }
        }
    }
}

// ============ standard grouped GEMM ============
template <bool RELU, bool SCATTER>
__global__ __launch_bounds__(256, 3) void k_gemm_mma(
    int lv, int Acode, int Kd, int Nd, size_t woff,
    const float* __restrict__ bias_base, int Ccode, float* __restrict__ outbuf)
{
    const int fid = (lv < L) ? g_tilefid[lv * NTM + blockIdx.x] : g_tilefidG[blockIdx.x];
    if (fid < 0) return;

    const int NC = Kd >> 5;

    const __nv_bfloat16 *Ahi, *Alo;
    if (Acode == 1) { Ahi = g_Y1hi; Alo = g_Y1lo; }
    else            { Ahi = g_Y2hi; Alo = g_Y2lo; }
    const __nv_bfloat16* __restrict__ Bhi = g_Whi + woff + (size_t)fid * Nd * Kd;
    const __nv_bfloat16* __restrict__ Blo = g_Wlo + woff + (size_t)fid * Nd * Kd;
    const float* __restrict__ bias = bias_base + (size_t)fid * Nd;

    const int rowBase = blockIdx.x * 128;
    const int colBase = blockIdx.y * BN;
    const int tid = threadIdx.x, lane = tid & 31, wid = tid >> 5;
    const int wmBase = (wid & 3) * 32;
    const int wnBase = (wid >> 2) * 32;
    const int gq = lane >> 2, tq = lane & 3;
    const int lrow = lane & 15, lcol = (lane >> 4) << 3;

    extern __shared__ __align__(16) unsigned short smem[];
    const uint32_t saddr = smem_u32(smem);

    float acc[2][4][4];
#pragma unroll
    for (int a = 0; a < 2; a++)
#pragma unroll
        for (int b = 0; b < 4; b++)
#pragma unroll
            for (int c = 0; c < 4; c++) acc[a][b][c] = 0.f;

    const int lr = tid >> 1, lp = tid & 1;
    auto issue = [&](int c, int st) {
        int k0 = c * 32;
        uint32_t dst = saddr + (uint32_t)(st * STAGEH + lr * SST + lp * 16) * 2;
        const __nv_bfloat16* ah = Ahi + (size_t)(rowBase + lr) * Kd + k0 + lp * 16;
        const __nv_bfloat16* al = Alo + (size_t)(rowBase + lr) * Kd + k0 + lp * 16;
        CPA16(dst, ah);                     CPA16(dst + 16, ah + 8);
        CPA16(dst + OFF_AL * 2, al);        CPA16(dst + OFF_AL * 2 + 16, al + 8);
        if (lr < BN) {
            const __nv_bfloat16* bh = Bhi + (size_t)(colBase + lr) * Kd + k0 + lp * 16;
            const __nv_bfloat16* bl = Blo + (size_t)(colBase + lr) * Kd + k0 + lp * 16;
            CPA16(dst + OFF_BH * 2, bh);    CPA16(dst + OFF_BH * 2 + 16, bh + 8);
            CPA16(dst + OFF_BL * 2, bl);    CPA16(dst + OFF_BL * 2 + 16, bl + 8);
        }
    };

    issue(0, 0); CPC();
    issue(1, 1); CPC();

    for (int c = 0; c < NC; c++) {
        const int st = c & 1;
        CPW1();
        __syncthreads();

        const uint32_t s0 = saddr + (uint32_t)(st * STAGEH) * 2;
        compute_kk(s0, wmBase, wnBase, lrow, lcol, 0,  acc);
        compute_kk(s0, wmBase, wnBase, lrow, lcol, 16, acc);

        __syncthreads();
        if (c + 2 < NC) issue(c + 2, st);
        CPC();
    }

    // ---- epilogue ----
    const int* perm = (lv < L) ? (g_perm + lv * PADM) : g_permG;

    if (SCATTER) {
        float* Cb;
        if (Ccode == 3)      Cb = g_hA;
        else if (Ccode == 4) Cb = g_hB;
        else                 Cb = outbuf;
#pragma unroll
        for (int mt = 0; mt < 2; mt++) {
#pragma unroll
            for (int hr = 0; hr < 2; hr++) {
                int row = rowBase + wmBase + mt * 16 + hr * 8 + gq;
                int dst = perm[row];
                if (dst < 0) continue;
#pragma unroll
                for (int nt = 0; nt < 4; nt++) {
                    int col = colBase + wnBase + nt * 8 + 2 * tq;
                    float2 v;
                    v.x = acc[mt][nt][hr * 2 + 0] + bias[col];
                    v.y = acc[mt][nt][hr * 2 + 1] + bias[col + 1];
                    if (RELU) { v.x = fmaxf(v.x, 0.f); v.y = fmaxf(v.y, 0.f); }
                    *(float2*)&Cb[(size_t)dst * Nd + col] = v;
                }
            }
        }
    } else {
        __nv_bfloat16* Chi = g_Y2hi;
        __nv_bfloat16* Clo = g_Y2lo;
#pragma unroll
        for (int mt = 0; mt < 2; mt++) {
#pragma unroll
            for (int hr = 0; hr < 2; hr++) {
                int row = rowBase + wmBase + mt * 16 + hr * 8 + gq;
#pragma unroll
                for (int nt = 0; nt < 4; nt++) {
                    int col = colBase + wnBase + nt * 8 + 2 * tq;
                    float vx = acc[mt][nt][hr * 2 + 0] + bias[col];
                    float vy = acc[mt][nt][hr * 2 + 1] + bias[col + 1];
                    if (RELU) { vx = fmaxf(vx, 0.f); vy = fmaxf(vy, 0.f); }
                    __nv_bfloat16 hx = __float2bfloat16(vx);
                    __nv_bfloat16 hy = __float2bfloat16(vy);
                    __nv_bfloat16 lx = __float2bfloat16(vx - __bfloat162float(hx));
                    __nv_bfloat16 ly = __float2bfloat16(vy - __bfloat162float(hy));
                    uint32_t hp  = ((uint32_t)__bfloat16_as_ushort(hy) << 16) | __bfloat16_as_ushort(hx);
                    uint32_t lp2 = ((uint32_t)__bfloat16_as_ushort(ly) << 16) | __bfloat16_as_ushort(lx);
                    size_t o = (size_t)row * Nd + col;
                    *(uint32_t*)&Chi[o] = hp;
                    *(uint32_t*)&Clo[o] = lp2;
                }
            }
        }
    }
}

// ---------------- launch ----------------
extern "C" void kernel_launch(void* const* d_in, const int* in_sizes, int n_in,
                              void* d_out, int out_size)
{
    const int*   leaf_ids = (const int*)d_in[0];
    const int*   left_idx = (const int*)d_in[1];
    const int*   right_idx= (const int*)d_in[2];
    const int*   nf_fid   = (const int*)d_in[3];
    const int*   gt_left  = (const int*)d_in[4];
    const int*   gt_right = (const int*)d_in[5];
    const int*   lf_fid   = (const int*)d_in[6];
    const float* emb      = (const float*)d_in[7];
    const float* W1 = (const float*)d_in[8];
    const float* b1 = (const float*)d_in[9];
    const float* W2 = (const float*)d_in[10];
    const float* b2 = (const float*)d_in[11];
    const float* W3 = (const float*)d_in[12];
    const float* b3 = (const float*)d_in[13];
    const float* Wl1= (const float*)d_in[14];
    const float* bl1= (const float*)d_in[15];
    const float* Wl2= (const float*)d_in[16];
    const float* bl2= (const float*)d_in[17];
    float* out = (float*)d_out;

    cudaFuncSetAttribute(k_gemm_fused,             cudaFuncAttributeMaxDynamicSharedMemorySize, GEMM_SMEM);
    cudaFuncSetAttribute(k_gemm_mma<true,  false>, cudaFuncAttributeMaxDynamicSharedMemorySize, GEMM_SMEM);
    cudaFuncSetAttribute(k_gemm_mma<false, true >, cudaFuncAttributeMaxDynamicSharedMemorySize, GEMM_SMEM);

    // grouping + weight prep
    k_reset<<<(L * PADM + 255) / 256, 256>>>();
    k_count<<<(L * M + G + 255) / 256, 256>>>(nf_fid, lf_fid);
    k_scatter_wconv<<<SCAT_BLOCKS + 3072, 256>>>(nf_fid, lf_fid, W1, W2, W3, Wl1, Wl2);

    int src = 0, dst = 3;   // 0 = emb (level 0), 3/4 = g_hA/g_hB
    for (int l = 0; l < L; l++) {
        dim3 g1(NTM, 8), g2(NTM, 4), g3(NTM, 2);
        k_gemm_fused<<<g1, 256, GEMM_SMEM>>>(l, left_idx + l * M, right_idx + l * M,
                                             src, emb, (l == 0) ? leaf_ids : nullptr,
                                             OFF_W1, b1);
        k_gemm_mma<true,  false><<<g2, 256, GEMM_SMEM>>>(l, 1, 512, 256, OFF_W2, b2, 2, nullptr);
        k_gemm_mma<false, true ><<<g3, 256, GEMM_SMEM>>>(l, 2, 256, 128, OFF_W3, b3, dst, nullptr);
        src = dst; dst = (dst == 3) ? 4 : 3;
    }

    // logic statements on final h (in buffer `src`)
    dim3 gl1(NTG, 8), gl2(NTG, 2);
    k_gemm_fused<<<gl1, 256, GEMM_SMEM>>>(L, gt_left, gt_right, src, emb, nullptr,
                                          OFF_WL1, bl1);
    k_gemm_mma<false, true ><<<gl2, 256, GEMM_SMEM>>>(L, 1, 512, 128, OFF_WL2, bl2, 5, out);
}

// round 13
// speedup vs baseline: 1.1503x; 1.1503x over previous
#include <cuda_runtime.h>
#include <cuda_bf16.h>
#include <cstdint>

// Problem constants
constexpr int D   = 128;
constexpr int M   = 8192;
constexpr int L   = 5;
constexpr int K   = 8;
constexpr int KL  = 4;
constexpr int G   = 4096;

constexpr int TILE = 128;
constexpr int PADM = M + K * TILE;    // 9216
constexpr int NTM  = PADM / TILE;     // 72
constexpr int PADG = G + KL * TILE;   // 4608
constexpr int NTG  = PADG / TILE;     // 36

// ---------------- device scratch (static; no allocation) ----------------
__device__ __align__(16) float g_hA[M * D];
__device__ __align__(16) float g_hB[M * D];

__device__ __align__(16) __nv_bfloat16 g_Y1hi[PADM * 512];
__device__ __align__(16) __nv_bfloat16 g_Y1lo[PADM * 512];
__device__ __align__(16) __nv_bfloat16 g_Y2hi[PADM * 256];
__device__ __align__(16) __nv_bfloat16 g_Y2lo[PADM * 256];

__device__ int g_perm   [L * PADM];
__device__ int g_tilefid[L * NTM];
__device__ int g_counts [L * K];
__device__ int g_cursor [L * K];
__device__ int g_offs   [L * K];

__device__ int g_permG   [PADG];
__device__ int g_tilefidG[NTG];
__device__ int g_countsG [KL];
__device__ int g_cursorG [KL];
__device__ int g_offsG   [KL];

// Weights transposed, layout [fid][n][Kd], separate hi/lo bf16
constexpr size_t OFF_W1  = 0;
constexpr size_t OFF_W2  = OFF_W1 + 8ull*512*256;
constexpr size_t OFF_W3  = OFF_W2 + 8ull*256*512;
constexpr size_t OFF_WL1 = OFF_W3 + 8ull*128*256;
constexpr size_t OFF_WL2 = OFF_WL1 + 4ull*512*256;
constexpr size_t WTOT    = OFF_WL2 + 4ull*128*512;
__device__ __align__(16) __nv_bfloat16 g_Whi[WTOT];
__device__ __align__(16) __nv_bfloat16 g_Wlo[WTOT];

// ---------------- PTX helpers ----------------
#define CPA16(dst, src) asm volatile("cp.async.cg.shared.global [%0], [%1], 16;" :: "r"(dst), "l"(src))
#define CPC()           asm volatile("cp.async.commit_group;" ::: "memory")
#define CPW1()          asm volatile("cp.async.wait_group 1;" ::: "memory")
#define LDSM4(r0, r1, r2, r3, a) \
    asm volatile("ldmatrix.sync.aligned.m8n8.x4.shared.b16 {%0,%1,%2,%3}, [%4];" \
        : "=r"(r0), "=r"(r1), "=r"(r2), "=r"(r3) : "r"(a))
#define MMA16816(acc, a0, a1, a2, a3, b0, b1) \
    asm volatile("mma.sync.aligned.m16n8k16.row.col.f32.bf16.bf16.f32 " \
        "{%0,%1,%2,%3}, {%4,%5,%6,%7}, {%8,%9}, {%0,%1,%2,%3};" \
        : "+f"((acc)[0]), "+f"((acc)[1]), "+f"((acc)[2]), "+f"((acc)[3]) \
        : "r"(a0), "r"(a1), "r"(a2), "r"(a3), "r"(b0), "r"(b1))

__device__ __forceinline__ uint32_t smem_u32(const void* p) {
    uint32_t a;
    asm("{ .reg .u64 t; cvta.to.shared.u64 t, %1; cvt.u32.u64 %0, t; }" : "=r"(a) : "l"(p));
    return a;
}

// ---------------- grouping kernels ----------------
__global__ void k_reset() {
    int t = blockIdx.x * blockDim.x + threadIdx.x;
    if (t < L * PADM) g_perm[t] = -1;
    if (t < PADG)     g_permG[t] = -1;
    if (t < L * NTM)  g_tilefid[t] = -1;
    if (t < NTG)      g_tilefidG[t] = -1;
    if (t < L * K)    { g_counts[t] = 0; g_cursor[t] = 0; }
    if (t < KL)       { g_countsG[t] = 0; g_cursorG[t] = 0; }
}

__global__ void k_count(const int* __restrict__ nf, const int* __restrict__ lf) {
    int t = blockIdx.x * blockDim.x + threadIdx.x;
    if (t < L * M) {
        int l = t / M;
        atomicAdd(&g_counts[l * K + nf[t]], 1);
    } else if (t < L * M + G) {
        atomicAdd(&g_countsG[lf[t - L * M]], 1);
    }
}

// 6 independent tasks (5 levels + logic)
__global__ void k_scan() {
    int i = threadIdx.x;
    if (i < L) {
        int l = i, off = 0;
        for (int k = 0; k < K; k++) {
            g_offs[l * K + k] = off;
            int nt = (g_counts[l * K + k] + TILE - 1) / TILE;
            for (int t = 0; t < nt; t++) g_tilefid[l * NTM + off / TILE + t] = k;
            off += nt * TILE;
        }
    } else if (i == L) {
        int off = 0;
        for (int k = 0; k < KL; k++) {
            g_offsG[k] = off;
            int nt = (g_countsG[k] + TILE - 1) / TILE;
            for (int t = 0; t < nt; t++) g_tilefidG[off / TILE + t] = k;
            off += nt * TILE;
        }
    }
}

constexpr int SCAT_BLOCKS = (L * M + G + 255) / 256;   // 176
__global__ void k_scatter_wconv(const int* __restrict__ nf, const int* __restrict__ lf,
                                const float* __restrict__ W1, const float* __restrict__ W2,
                                const float* __restrict__ W3, const float* __restrict__ Wl1,
                                const float* __restrict__ Wl2) {
    if (blockIdx.x < SCAT_BLOCKS) {
        int t = blockIdx.x * blockDim.x + threadIdx.x;
        if (t < L * M) {
            int l = t / M, m = t % M;
            int f = nf[t];
            int pos = g_offs[l * K + f] + atomicAdd(&g_cursor[l * K + f], 1);
            g_perm[l * PADM + pos] = m;
        } else if (t < L * M + G) {
            int s = t - L * M;
            int f = lf[s];
            int pos = g_offsG[f] + atomicAdd(&g_cursorG[f], 1);
            g_permG[pos] = s;
        }
        return;
    }
    __shared__ float ts[32][33];
    int tix = blockIdx.x - SCAT_BLOCKS;
    const float* W; size_t woff; int Kd, Nd;
    if (tix < 1024)      { W = W1;  woff = OFF_W1;  Kd = 256; Nd = 512; }
    else if (tix < 2048) { W = W2;  woff = OFF_W2;  Kd = 512; Nd = 256; tix -= 1024; }
    else if (tix < 2304) { W = W3;  woff = OFF_W3;  Kd = 256; Nd = 128; tix -= 2048; }
    else if (tix < 2816) { W = Wl1; woff = OFF_WL1; Kd = 256; Nd = 512; tix -= 2304; }
    else                 { W = Wl2; woff = OFF_WL2; Kd = 512; Nd = 128; tix -= 2816; }
    int ntk = Kd / 32;
    int per = ntk * (Nd / 32);
    int f = tix / per, rem = tix % per;
    int n0 = (rem / ntk) * 32, k0 = (rem % ntk) * 32;
    int tx = threadIdx.x & 31, ty = threadIdx.x >> 5;

    const float* Wf = W + (size_t)f * Kd * Nd;
    for (int rr = ty; rr < 32; rr += 8)
        ts[rr][tx] = Wf[(size_t)(k0 + rr) * Nd + n0 + tx];
    __syncthreads();
    for (int rr = ty; rr < 32; rr += 8) {
        float x = ts[tx][rr];
        __nv_bfloat16 h = __float2bfloat16(x);
        __nv_bfloat16 l = __float2bfloat16(x - __bfloat162float(h));
        size_t o = woff + (size_t)f * Nd * Kd + (size_t)(n0 + rr) * Kd + k0 + tx;
        g_Whi[o] = h;
        g_Wlo[o] = l;
    }
}

// ---------------- GEMM geometry: BN=64, 3 stages ----------------
constexpr int SST = 40;                        // halves per smem row
constexpr int BN  = 64;
constexpr int OFF_AL = 128 * SST;
constexpr int OFF_BH = 256 * SST;
constexpr int OFF_BL = 256 * SST + BN * SST;
constexpr int STAGEH = (256 + 2 * BN) * SST;   // halves per stage
constexpr int GEMM_SMEM = 3 * STAGEH * 2;      // 92160 B

// compute one 16-wide K slice. Warp grid 4m x 2n, warp tile 32x32.
// 3 products; per warp: 4 A-LDSM4 + 4 B-LDSM4 for 24 MMAs.
__device__ __forceinline__ void compute_kk(
    uint32_t s0, int wmBase, int wnBase, int lrow, int lcol, int kk, float (*acc)[4][4])
{
    uint32_t ah[2][4], al[2][4];
#pragma unroll
    for (int mt = 0; mt < 2; mt++) {
        uint32_t ad = s0 + (uint32_t)((wmBase + mt * 16 + lrow) * SST + kk + lcol) * 2;
        LDSM4(ah[mt][0], ah[mt][1], ah[mt][2], ah[mt][3], ad);
        LDSM4(al[mt][0], al[mt][1], al[mt][2], al[mt][3], ad + OFF_AL * 2);
    }
    uint32_t bb[4][2];
#pragma unroll
    for (int p = 0; p < 2; p++) {
        uint32_t r0, r1, r2, r3;
        uint32_t ad = s0 + (uint32_t)(OFF_BH + (wnBase + p * 16 + lrow) * SST + kk + lcol) * 2;
        LDSM4(r0, r1, r2, r3, ad);
        bb[2 * p][0] = r0; bb[2 * p + 1][0] = r1;
        bb[2 * p][1] = r2; bb[2 * p + 1][1] = r3;
    }
#pragma unroll
    for (int mt = 0; mt < 2; mt++)
#pragma unroll
        for (int nt = 0; nt < 4; nt++)
            MMA16816(acc[mt][nt], ah[mt][0], ah[mt][1], ah[mt][2], ah[mt][3], bb[nt][0], bb[nt][1]);
#pragma unroll
    for (int mt = 0; mt < 2; mt++)
#pragma unroll
        for (int nt = 0; nt < 4; nt++)
            MMA16816(acc[mt][nt], al[mt][0], al[mt][1], al[mt][2], al[mt][3], bb[nt][0], bb[nt][1]);
#pragma unroll
    for (int p = 0; p < 2; p++) {
        uint32_t r0, r1, r2, r3;
        uint32_t ad = s0 + (uint32_t)(OFF_BL + (wnBase + p * 16 + lrow) * SST + kk + lcol) * 2;
        LDSM4(r0, r1, r2, r3, ad);
        bb[2 * p][0] = r0; bb[2 * p + 1][0] = r1;
        bb[2 * p][1] = r2; bb[2 * p + 1][1] = r3;
    }
#pragma unroll
    for (int mt = 0; mt < 2; mt++)
#pragma unroll
        for (int nt = 0; nt < 4; nt++)
            MMA16816(acc[mt][nt], ah[mt][0], ah[mt][1], ah[mt][2], ah[mt][3], bb[nt][0], bb[nt][1]);
}

// ============ fused gather + GEMM1 ============
__global__ __launch_bounds__(256, 2) void k_gemm_fused(
    int lv, const int* __restrict__ li, const int* __restrict__ ri,
    int hsel, const float* __restrict__ emb, const int* __restrict__ lmap,
    size_t woff, const float* __restrict__ bias_base)
{
    const int fid = (lv < L) ? g_tilefid[lv * NTM + blockIdx.x] : g_tilefidG[blockIdx.x];
    if (fid < 0) return;

    constexpr int Kd = 256, Nd = 512;
    constexpr int NC = Kd / 32;                // 8

    const float* hsrc = (hsel == 0) ? emb : ((hsel == 3) ? g_hA : g_hB);
    const __nv_bfloat16* __restrict__ Bhi = g_Whi + woff + (size_t)fid * Nd * Kd;
    const __nv_bfloat16* __restrict__ Blo = g_Wlo + woff + (size_t)fid * Nd * Kd;
    const float* __restrict__ bias = bias_base + (size_t)fid * Nd;

    const int rowBase = blockIdx.x * 128;
    const int colBase = blockIdx.y * BN;
    const int tid = threadIdx.x, lane = tid & 31, wid = tid >> 5;
    const int wmBase = (wid & 3) * 32;
    const int wnBase = (wid >> 2) * 32;
    const int gq = lane >> 2, tq = lane & 3;
    const int lrow = lane & 15, lcol = (lane >> 4) << 3;

    extern __shared__ __align__(16) unsigned short smem[];
    const uint32_t saddr = smem_u32(smem);

    float acc[2][4][4];
#pragma unroll
    for (int a = 0; a < 2; a++)
#pragma unroll
        for (int b = 0; b < 4; b++)
#pragma unroll
            for (int c = 0; c < 4; c++) acc[a][b][c] = 0.f;

    const int lr = tid >> 1, lp = tid & 1;
    const int* perm = (lv < L) ? (g_perm + lv * PADM) : g_permG;
    const int node = perm[rowBase + lr];
    const float* pL = nullptr;
    const float* pR = nullptr;
    if (node >= 0) {
        int il = li[node], ir = ri[node];
        if (lmap) { il = lmap[il]; ir = lmap[ir]; }
        pL = hsrc + (size_t)il * 128 + lp * 16;
        pR = hsrc + (size_t)ir * 128 + lp * 16;
    }

    float4 pa[4];
    auto ldA = [&](int c) {
        if (node >= 0) {
            const float* base = ((c < 4) ? pL : pR) + (c & 3) * 32;
#pragma unroll
            for (int j = 0; j < 4; j++) pa[j] = *(const float4*)(base + 4 * j);
        } else {
#pragma unroll
            for (int j = 0; j < 4; j++) pa[j] = make_float4(0.f, 0.f, 0.f, 0.f);
        }
    };
    auto stsA = [&](int st) {
        __align__(16) __nv_bfloat16 hi16[16], lo16[16];
        const float* v = (const float*)pa;
#pragma unroll
        for (int i = 0; i < 16; i++) {
            __nv_bfloat16 h = __float2bfloat16(v[i]);
            hi16[i] = h;
            lo16[i] = __float2bfloat16(v[i] - __bfloat162float(h));
        }
        unsigned short* dh = smem + st * STAGEH + lr * SST + lp * 16;
        *(uint4*)(dh)              = *(uint4*)&hi16[0];
        *(uint4*)(dh + 8)          = *(uint4*)&hi16[8];
        *(uint4*)(dh + OFF_AL)     = *(uint4*)&lo16[0];
        *(uint4*)(dh + OFF_AL + 8) = *(uint4*)&lo16[8];
    };
    auto issueB = [&](int c, int st) {
        if (lr < BN) {
            int k0 = c * 32;
            uint32_t dst = saddr + (uint32_t)(st * STAGEH + lr * SST + lp * 16) * 2;
            const __nv_bfloat16* bh = Bhi + (size_t)(colBase + lr) * Kd + k0 + lp * 16;
            const __nv_bfloat16* bl = Blo + (size_t)(colBase + lr) * Kd + k0 + lp * 16;
            CPA16(dst + OFF_BH * 2, bh);    CPA16(dst + OFF_BH * 2 + 16, bh + 8);
            CPA16(dst + OFF_BL * 2, bl);    CPA16(dst + OFF_BL * 2 + 16, bl + 8);
        }
    };

    // prologue: A0 in smem, A1 in regs, B0/B1 in flight
    ldA(0); stsA(0);
    ldA(1);
    issueB(0, 0); CPC();
    issueB(1, 1); CPC();

    for (int c = 0; c < NC; c++) {
        const int st = c % 3;
        CPW1();
        __syncthreads();
        if (c + 1 < NC) stsA((c + 1) % 3);
        if (c + 2 < NC) ldA(c + 2);
        if (c + 2 < NC) issueB(c + 2, (c + 2) % 3);
        CPC();

        const uint32_t s0 = saddr + (uint32_t)(st * STAGEH) * 2;
        compute_kk(s0, wmBase, wnBase, lrow, lcol, 0,  acc);
        compute_kk(s0, wmBase, wnBase, lrow, lcol, 16, acc);
    }

    // epilogue: relu, split hi/lo -> Y1
#pragma unroll
    for (int mt = 0; mt < 2; mt++) {
#pragma unroll
        for (int hr = 0; hr < 2; hr++) {
            int row = rowBase + wmBase + mt * 16 + hr * 8 + gq;
#pragma unroll
            for (int nt = 0; nt < 4; nt++) {
                int col = colBase + wnBase + nt * 8 + 2 * tq;
                float vx = fmaxf(acc[mt][nt][hr * 2 + 0] + bias[col], 0.f);
                float vy = fmaxf(acc[mt][nt][hr * 2 + 1] + bias[col + 1], 0.f);
                __nv_bfloat16 hx = __float2bfloat16(vx);
                __nv_bfloat16 hy = __float2bfloat16(vy);
                __nv_bfloat16 lx = __float2bfloat16(vx - __bfloat162float(hx));
                __nv_bfloat16 ly = __float2bfloat16(vy - __bfloat162float(hy));
                uint32_t hp  = ((uint32_t)__bfloat16_as_ushort(hy) << 16) | __bfloat16_as_ushort(hx);
                uint32_t lp2 = ((uint32_t)__bfloat16_as_ushort(ly) << 16) | __bfloat16_as_ushort(lx);
                size_t o = (size_t)row * Nd + col;
                *(uint32_t*)&g_Y1hi[o] = hp;
                *(uint32_t*)&g_Y1lo[o] = lp2;
            }
        }
    }
}

// ============ standard grouped GEMM ============
template <bool RELU, bool SCATTER>
__global__ __launch_bounds__(256, 2) void k_gemm_mma(
    int lv, int Acode, int Kd, int Nd, size_t woff,
    const float* __restrict__ bias_base, int Ccode, float* __restrict__ outbuf)
{
    const int fid = (lv < L) ? g_tilefid[lv * NTM + blockIdx.x] : g_tilefidG[blockIdx.x];
    if (fid < 0) return;

    const int NC = Kd >> 5;

    const __nv_bfloat16 *Ahi, *Alo;
    if (Acode == 1) { Ahi = g_Y1hi; Alo = g_Y1lo; }
    else            { Ahi = g_Y2hi; Alo = g_Y2lo; }
    const __nv_bfloat16* __restrict__ Bhi = g_Whi + woff + (size_t)fid * Nd * Kd;
    const __nv_bfloat16* __restrict__ Blo = g_Wlo + woff + (size_t)fid * Nd * Kd;
    const float* __restrict__ bias = bias_base + (size_t)fid * Nd;

    const int rowBase = blockIdx.x * 128;
    const int colBase = blockIdx.y * BN;
    const int tid = threadIdx.x, lane = tid & 31, wid = tid >> 5;
    const int wmBase = (wid & 3) * 32;
    const int wnBase = (wid >> 2) * 32;
    const int gq = lane >> 2, tq = lane & 3;
    const int lrow = lane & 15, lcol = (lane >> 4) << 3;

    extern __shared__ __align__(16) unsigned short smem[];
    const uint32_t saddr = smem_u32(smem);

    float acc[2][4][4];
#pragma unroll
    for (int a = 0; a < 2; a++)
#pragma unroll
        for (int b = 0; b < 4; b++)
#pragma unroll
            for (int c = 0; c < 4; c++) acc[a][b][c] = 0.f;

    const int lr = tid >> 1, lp = tid & 1;
    auto issue = [&](int c, int st) {
        int k0 = c * 32;
        uint32_t dst = saddr + (uint32_t)(st * STAGEH + lr * SST + lp * 16) * 2;
        const __nv_bfloat16* ah = Ahi + (size_t)(rowBase + lr) * Kd + k0 + lp * 16;
        const __nv_bfloat16* al = Alo + (size_t)(rowBase + lr) * Kd + k0 + lp * 16;
        CPA16(dst, ah);                     CPA16(dst + 16, ah + 8);
        CPA16(dst + OFF_AL * 2, al);        CPA16(dst + OFF_AL * 2 + 16, al + 8);
        if (lr < BN) {
            const __nv_bfloat16* bh = Bhi + (size_t)(colBase + lr) * Kd + k0 + lp * 16;
            const __nv_bfloat16* bl = Blo + (size_t)(colBase + lr) * Kd + k0 + lp * 16;
            CPA16(dst + OFF_BH * 2, bh);    CPA16(dst + OFF_BH * 2 + 16, bh + 8);
            CPA16(dst + OFF_BL * 2, bl);    CPA16(dst + OFF_BL * 2 + 16, bl + 8);
        }
    };

    issue(0, 0); CPC();
    issue(1, 1); CPC();

    for (int c = 0; c < NC; c++) {
        const int st = c % 3;
        CPW1();
        __syncthreads();
        if (c + 2 < NC) issue(c + 2, (c + 2) % 3);
        CPC();

        const uint32_t s0 = saddr + (uint32_t)(st * STAGEH) * 2;
        compute_kk(s0, wmBase, wnBase, lrow, lcol, 0,  acc);
        compute_kk(s0, wmBase, wnBase, lrow, lcol, 16, acc);
    }

    // ---- epilogue ----
    const int* perm = (lv < L) ? (g_perm + lv * PADM) : g_permG;

    if (SCATTER) {
        float* Cb;
        if (Ccode == 3)      Cb = g_hA;
        else if (Ccode == 4) Cb = g_hB;
        else                 Cb = outbuf;
#pragma unroll
        for (int mt = 0; mt < 2; mt++) {
#pragma unroll
            for (int hr = 0; hr < 2; hr++) {
                int row = rowBase + wmBase + mt * 16 + hr * 8 + gq;
                int dst = perm[row];
                if (dst < 0) continue;
#pragma unroll
                for (int nt = 0; nt < 4; nt++) {
                    int col = colBase + wnBase + nt * 8 + 2 * tq;
                    float2 v;
                    v.x = acc[mt][nt][hr * 2 + 0] + bias[col];
                    v.y = acc[mt][nt][hr * 2 + 1] + bias[col + 1];
                    if (RELU) { v.x = fmaxf(v.x, 0.f); v.y = fmaxf(v.y, 0.f); }
                    *(float2*)&Cb[(size_t)dst * Nd + col] = v;
                }
            }
        }
    } else {
        __nv_bfloat16* Chi = g_Y2hi;
        __nv_bfloat16* Clo = g_Y2lo;
#pragma unroll
        for (int mt = 0; mt < 2; mt++) {
#pragma unroll
            for (int hr = 0; hr < 2; hr++) {
                int row = rowBase + wmBase + mt * 16 + hr * 8 + gq;
#pragma unroll
                for (int nt = 0; nt < 4; nt++) {
                    int col = colBase + wnBase + nt * 8 + 2 * tq;
                    float vx = acc[mt][nt][hr * 2 + 0] + bias[col];
                    float vy = acc[mt][nt][hr * 2 + 1] + bias[col + 1];
                    if (RELU) { vx = fmaxf(vx, 0.f); vy = fmaxf(vy, 0.f); }
                    __nv_bfloat16 hx = __float2bfloat16(vx);
                    __nv_bfloat16 hy = __float2bfloat16(vy);
                    __nv_bfloat16 lx = __float2bfloat16(vx - __bfloat162float(hx));
                    __nv_bfloat16 ly = __float2bfloat16(vy - __bfloat162float(hy));
                    uint32_t hp  = ((uint32_t)__bfloat16_as_ushort(hy) << 16) | __bfloat16_as_ushort(hx);
                    uint32_t lp2 = ((uint32_t)__bfloat16_as_ushort(ly) << 16) | __bfloat16_as_ushort(lx);
                    size_t o = (size_t)row * Nd + col;
                    *(uint32_t*)&Chi[o] = hp;
                    *(uint32_t*)&Clo[o] = lp2;
                }
            }
        }
    }
}

// ---------------- launch ----------------
extern "C" void kernel_launch(void* const* d_in, const int* in_sizes, int n_in,
                              void* d_out, int out_size)
{
    const int*   leaf_ids = (const int*)d_in[0];
    const int*   left_idx = (const int*)d_in[1];
    const int*   right_idx= (const int*)d_in[2];
    const int*   nf_fid   = (const int*)d_in[3];
    const int*   gt_left  = (const int*)d_in[4];
    const int*   gt_right = (const int*)d_in[5];
    const int*   lf_fid   = (const int*)d_in[6];
    const float* emb      = (const float*)d_in[7];
    const float* W1 = (const float*)d_in[8];
    const float* b1 = (const float*)d_in[9];
    const float* W2 = (const float*)d_in[10];
    const float* b2 = (const float*)d_in[11];
    const float* W3 = (const float*)d_in[12];
    const float* b3 = (const float*)d_in[13];
    const float* Wl1= (const float*)d_in[14];
    const float* bl1= (const float*)d_in[15];
    const float* Wl2= (const float*)d_in[16];
    const float* bl2= (const float*)d_in[17];
    float* out = (float*)d_out;

    cudaFuncSetAttribute(k_gemm_fused,             cudaFuncAttributeMaxDynamicSharedMemorySize, GEMM_SMEM);
    cudaFuncSetAttribute(k_gemm_mma<true,  false>, cudaFuncAttributeMaxDynamicSharedMemorySize, GEMM_SMEM);
    cudaFuncSetAttribute(k_gemm_mma<false, true >, cudaFuncAttributeMaxDynamicSharedMemorySize, GEMM_SMEM);

    // grouping + weight prep
    k_reset<<<(L * PADM + 255) / 256, 256>>>();
    k_count<<<(L * M + G + 255) / 256, 256>>>(nf_fid, lf_fid);
    k_scan <<<1, 32>>>();
    k_scatter_wconv<<<SCAT_BLOCKS + 3072, 256>>>(nf_fid, lf_fid, W1, W2, W3, Wl1, Wl2);

    int src = 0, dst = 3;   // 0 = emb (level 0), 3/4 = g_hA/g_hB
    for (int l = 0; l < L; l++) {
        dim3 g1(NTM, 8), g2(NTM, 4), g3(NTM, 2);
        k_gemm_fused<<<g1, 256, GEMM_SMEM>>>(l, left_idx + l * M, right_idx + l * M,
                                             src, emb, (l == 0) ? leaf_ids : nullptr,
                                             OFF_W1, b1);
        k_gemm_mma<true,  false><<<g2, 256, GEMM_SMEM>>>(l, 1, 512, 256, OFF_W2, b2, 2, nullptr);
        k_gemm_mma<false, true ><<<g3, 256, GEMM_SMEM>>>(l, 2, 256, 128, OFF_W3, b3, dst, nullptr);
        src = dst; dst = (dst == 3) ? 4 : 3;
    }

    // logic statements on final h (in buffer `src`)
    dim3 gl1(NTG, 8), gl2(NTG, 2);
    k_gemm_fused<<<gl1, 256, GEMM_SMEM>>>(L, gt_left, gt_right, src, emb, nullptr,
                                          OFF_WL1, bl1);
    k_gemm_mma<false, true ><<<gl2, 256, GEMM_SMEM>>>(L, 1, 512, 128, OFF_WL2, bl2, 5, out);
}

// round 14
// speedup vs baseline: 1.1856x; 1.0307x over previous
#include <cuda_runtime.h>
#include <cuda_bf16.h>
#include <cstdint>

// Problem constants
constexpr int D   = 128;
constexpr int M   = 8192;
constexpr int L   = 5;
constexpr int K   = 8;
constexpr int KL  = 4;
constexpr int G   = 4096;

constexpr int TILE = 128;
constexpr int PADM = M + K * TILE;    // 9216
constexpr int NTM  = PADM / TILE;     // 72
constexpr int PADG = G + KL * TILE;   // 4608
constexpr int NTG  = PADG / TILE;     // 36

// ---------------- device scratch (static; no allocation) ----------------
__device__ __align__(16) float g_hA[M * D];
__device__ __align__(16) float g_hB[M * D];

__device__ __align__(16) __nv_bfloat16 g_Y1hi[PADM * 512];
__device__ __align__(16) __nv_bfloat16 g_Y1lo[PADM * 512];
__device__ __align__(16) __nv_bfloat16 g_Y2hi[PADM * 256];
__device__ __align__(16) __nv_bfloat16 g_Y2lo[PADM * 256];

__device__ int g_perm   [L * PADM];
__device__ int g_tilefid[L * NTM];
__device__ int g_counts [L * K];
__device__ int g_cursor [L * K];
__device__ int g_offs   [L * K];

__device__ int g_permG   [PADG];
__device__ int g_tilefidG[NTG];
__device__ int g_countsG [KL];
__device__ int g_cursorG [KL];
__device__ int g_offsG   [KL];

// Weights transposed, layout [fid][n][Kd], separate hi/lo bf16
constexpr size_t OFF_W1  = 0;
constexpr size_t OFF_W2  = OFF_W1 + 8ull*512*256;
constexpr size_t OFF_W3  = OFF_W2 + 8ull*256*512;
constexpr size_t OFF_WL1 = OFF_W3 + 8ull*128*256;
constexpr size_t OFF_WL2 = OFF_WL1 + 4ull*512*256;
constexpr size_t WTOT    = OFF_WL2 + 4ull*128*512;
__device__ __align__(16) __nv_bfloat16 g_Whi[WTOT];
__device__ __align__(16) __nv_bfloat16 g_Wlo[WTOT];

// ---------------- PTX helpers ----------------
#define CPA16(dst, src) asm volatile("cp.async.cg.shared.global [%0], [%1], 16;" :: "r"(dst), "l"(src))
#define CPC()           asm volatile("cp.async.commit_group;" ::: "memory")
#define CPW1()          asm volatile("cp.async.wait_group 1;" ::: "memory")
#define LDSM4(r0, r1, r2, r3, a) \
    asm volatile("ldmatrix.sync.aligned.m8n8.x4.shared.b16 {%0,%1,%2,%3}, [%4];" \
        : "=r"(r0), "=r"(r1), "=r"(r2), "=r"(r3) : "r"(a))
#define MMA16816(acc, a0, a1, a2, a3, b0, b1) \
    asm volatile("mma.sync.aligned.m16n8k16.row.col.f32.bf16.bf16.f32 " \
        "{%0,%1,%2,%3}, {%4,%5,%6,%7}, {%8,%9}, {%0,%1,%2,%3};" \
        : "+f"((acc)[0]), "+f"((acc)[1]), "+f"((acc)[2]), "+f"((acc)[3]) \
        : "r"(a0), "r"(a1), "r"(a2), "r"(a3), "r"(b0), "r"(b1))

__device__ __forceinline__ uint32_t smem_u32(const void* p) {
    uint32_t a;
    asm("{ .reg .u64 t; cvta.to.shared.u64 t, %1; cvt.u32.u64 %0, t; }" : "=r"(a) : "l"(p));
    return a;
}

// ---------------- grouping kernels ----------------
__global__ void k_reset() {
    int t = blockIdx.x * blockDim.x + threadIdx.x;
    if (t < L * PADM) g_perm[t] = -1;
    if (t < PADG)     g_permG[t] = -1;
    if (t < L * NTM)  g_tilefid[t] = -1;
    if (t < NTG)      g_tilefidG[t] = -1;
    if (t < L * K)    { g_counts[t] = 0; g_cursor[t] = 0; }
    if (t < KL)       { g_countsG[t] = 0; g_cursorG[t] = 0; }
}

__global__ void k_count(const int* __restrict__ nf, const int* __restrict__ lf) {
    int t = blockIdx.x * blockDim.x + threadIdx.x;
    if (t < L * M) {
        int l = t / M;
        atomicAdd(&g_counts[l * K + nf[t]], 1);
    } else if (t < L * M + G) {
        atomicAdd(&g_countsG[lf[t - L * M]], 1);
    }
}

__global__ void k_scan() {
    int i = threadIdx.x;
    if (i < L) {
        int l = i, off = 0;
        for (int k = 0; k < K; k++) {
            g_offs[l * K + k] = off;
            int nt = (g_counts[l * K + k] + TILE - 1) / TILE;
            for (int t = 0; t < nt; t++) g_tilefid[l * NTM + off / TILE + t] = k;
            off += nt * TILE;
        }
    } else if (i == L) {
        int off = 0;
        for (int k = 0; k < KL; k++) {
            g_offsG[k] = off;
            int nt = (g_countsG[k] + TILE - 1) / TILE;
            for (int t = 0; t < nt; t++) g_tilefidG[off / TILE + t] = k;
            off += nt * TILE;
        }
    }
}

constexpr int SCAT_BLOCKS = (L * M + G + 255) / 256;   // 176
__global__ void k_scatter_wconv(const int* __restrict__ nf, const int* __restrict__ lf,
                                const float* __restrict__ W1, const float* __restrict__ W2,
                                const float* __restrict__ W3, const float* __restrict__ Wl1,
                                const float* __restrict__ Wl2) {
    if (blockIdx.x < SCAT_BLOCKS) {
        int t = blockIdx.x * blockDim.x + threadIdx.x;
        if (t < L * M) {
            int l = t / M, m = t % M;
            int f = nf[t];
            int pos = g_offs[l * K + f] + atomicAdd(&g_cursor[l * K + f], 1);
            g_perm[l * PADM + pos] = m;
        } else if (t < L * M + G) {
            int s = t - L * M;
            int f = lf[s];
            int pos = g_offsG[f] + atomicAdd(&g_cursorG[f], 1);
            g_permG[pos] = s;
        }
        return;
    }
    __shared__ float ts[32][33];
    int tix = blockIdx.x - SCAT_BLOCKS;
    const float* W; size_t woff; int Kd, Nd;
    if (tix < 1024)      { W = W1;  woff = OFF_W1;  Kd = 256; Nd = 512; }
    else if (tix < 2048) { W = W2;  woff = OFF_W2;  Kd = 512; Nd = 256; tix -= 1024; }
    else if (tix < 2304) { W = W3;  woff = OFF_W3;  Kd = 256; Nd = 128; tix -= 2048; }
    else if (tix < 2816) { W = Wl1; woff = OFF_WL1; Kd = 256; Nd = 512; tix -= 2304; }
    else                 { W = Wl2; woff = OFF_WL2; Kd = 512; Nd = 128; tix -= 2816; }
    int ntk = Kd / 32;
    int per = ntk * (Nd / 32);
    int f = tix / per, rem = tix % per;
    int n0 = (rem / ntk) * 32, k0 = (rem % ntk) * 32;
    int tx = threadIdx.x & 31, ty = threadIdx.x >> 5;

    const float* Wf = W + (size_t)f * Kd * Nd;
    for (int rr = ty; rr < 32; rr += 8)
        ts[rr][tx] = Wf[(size_t)(k0 + rr) * Nd + n0 + tx];
    __syncthreads();
    for (int rr = ty; rr < 32; rr += 8) {
        float x = ts[tx][rr];
        __nv_bfloat16 h = __float2bfloat16(x);
        __nv_bfloat16 l = __float2bfloat16(x - __bfloat162float(h));
        size_t o = woff + (size_t)f * Nd * Kd + (size_t)(n0 + rr) * Kd + k0 + tx;
        g_Whi[o] = h;
        g_Wlo[o] = l;
    }
}

// ---------------- GEMM geometry ----------------
constexpr int SST = 40;                        // halves per smem row
constexpr int OFF_AL = 128 * SST;
constexpr int OFF_BH = 256 * SST;

template <int BN_> struct Geo {
    static constexpr int STAGES = (BN_ == 128) ? 2 : 3;
    static constexpr int STAGEH = (256 + 2 * BN_) * SST;
    static constexpr int OFF_BL = 256 * SST + BN_ * SST;
    static constexpr int SMEM   = STAGES * STAGEH * 2;
};

// one 16-wide K slice, warp grid 4m x 2n, warp tile 32 x (BN_/2).
// B processed in 32-col groups to bound live registers.
template <int BN_>
__device__ __forceinline__ void compute_kk(
    uint32_t s0, int wmBase, int wnBase, int lrow, int lcol, int kk, float (*acc)[4])
{
    constexpr int NT = BN_ / 16;
    constexpr int NG = NT / 4;
    uint32_t ah[2][4], al[2][4];
#pragma unroll
    for (int mt = 0; mt < 2; mt++) {
        uint32_t ad = s0 + (uint32_t)((wmBase + mt * 16 + lrow) * SST + kk + lcol) * 2;
        LDSM4(ah[mt][0], ah[mt][1], ah[mt][2], ah[mt][3], ad);
        LDSM4(al[mt][0], al[mt][1], al[mt][2], al[mt][3], ad + OFF_AL * 2);
    }
#pragma unroll
    for (int g = 0; g < NG; g++) {
        uint32_t bb[4][2];
#pragma unroll
        for (int p = 0; p < 2; p++) {
            uint32_t r0, r1, r2, r3;
            uint32_t ad = s0 + (uint32_t)(OFF_BH + (wnBase + g * 32 + p * 16 + lrow) * SST + kk + lcol) * 2;
            LDSM4(r0, r1, r2, r3, ad);
            bb[2 * p][0] = r0; bb[2 * p + 1][0] = r1;
            bb[2 * p][1] = r2; bb[2 * p + 1][1] = r3;
        }
#pragma unroll
        for (int mt = 0; mt < 2; mt++)
#pragma unroll
            for (int j = 0; j < 4; j++)
                MMA16816(acc[mt * NT + g * 4 + j], ah[mt][0], ah[mt][1], ah[mt][2], ah[mt][3], bb[j][0], bb[j][1]);
#pragma unroll
        for (int mt = 0; mt < 2; mt++)
#pragma unroll
            for (int j = 0; j < 4; j++)
                MMA16816(acc[mt * NT + g * 4 + j], al[mt][0], al[mt][1], al[mt][2], al[mt][3], bb[j][0], bb[j][1]);
#pragma unroll
        for (int p = 0; p < 2; p++) {
            uint32_t r0, r1, r2, r3;
            uint32_t ad = s0 + (uint32_t)(Geo<BN_>::OFF_BL + (wnBase + g * 32 + p * 16 + lrow) * SST + kk + lcol) * 2;
            LDSM4(r0, r1, r2, r3, ad);
            bb[2 * p][0] = r0; bb[2 * p + 1][0] = r1;
            bb[2 * p][1] = r2; bb[2 * p + 1][1] = r3;
        }
#pragma unroll
        for (int mt = 0; mt < 2; mt++)
#pragma unroll
            for (int j = 0; j < 4; j++)
                MMA16816(acc[mt * NT + g * 4 + j], ah[mt][0], ah[mt][1], ah[mt][2], ah[mt][3], bb[j][0], bb[j][1]);
    }
}

// ============ fused gather + GEMM1 (BN=128, 2-stage) ============
__global__ __launch_bounds__(256, 2) void k_gemm_fused(
    int lv, const int* __restrict__ li, const int* __restrict__ ri,
    int hsel, const float* __restrict__ emb, const int* __restrict__ lmap,
    size_t woff, const float* __restrict__ bias_base)
{
    const int fid = (lv < L) ? g_tilefid[lv * NTM + blockIdx.x] : g_tilefidG[blockIdx.x];
    if (fid < 0) return;

    constexpr int BN_ = 128;
    constexpr int NT = BN_ / 16;               // 8
    constexpr int STAGEH = Geo<BN_>::STAGEH;
    constexpr int Kd = 256, Nd = 512;
    constexpr int NC = Kd / 32;                // 8

    const float* hsrc = (hsel == 0) ? emb : ((hsel == 3) ? g_hA : g_hB);
    const __nv_bfloat16* __restrict__ Bhi = g_Whi + woff + (size_t)fid * Nd * Kd;
    const __nv_bfloat16* __restrict__ Blo = g_Wlo + woff + (size_t)fid * Nd * Kd;
    const float* __restrict__ bias = bias_base + (size_t)fid * Nd;

    const int rowBase = blockIdx.x * 128;
    const int colBase = blockIdx.y * BN_;
    const int tid = threadIdx.x, lane = tid & 31, wid = tid >> 5;
    const int wmBase = (wid & 3) * 32;
    const int wnBase = (wid >> 2) * (BN_ / 2);
    const int gq = lane >> 2, tq = lane & 3;
    const int lrow = lane & 15, lcol = (lane >> 4) << 3;

    extern __shared__ __align__(16) unsigned short smem[];
    const uint32_t saddr = smem_u32(smem);

    float acc[2 * NT][4];
#pragma unroll
    for (int b = 0; b < 2 * NT; b++)
#pragma unroll
        for (int c = 0; c < 4; c++) acc[b][c] = 0.f;

    const int lr = tid >> 1, lp = tid & 1;
    const int* perm = (lv < L) ? (g_perm + lv * PADM) : g_permG;
    const int node = perm[rowBase + lr];
    const float* pL = nullptr;
    const float* pR = nullptr;
    if (node >= 0) {
        int il = li[node], ir = ri[node];
        if (lmap) { il = lmap[il]; ir = lmap[ir]; }
        pL = hsrc + (size_t)il * 128 + lp * 16;
        pR = hsrc + (size_t)ir * 128 + lp * 16;
    }

    float4 pa[4];
    auto ldA = [&](int c) {
        if (node >= 0) {
            const float* base = ((c < 4) ? pL : pR) + (c & 3) * 32;
#pragma unroll
            for (int j = 0; j < 4; j++) pa[j] = *(const float4*)(base + 4 * j);
        } else {
#pragma unroll
            for (int j = 0; j < 4; j++) pa[j] = make_float4(0.f, 0.f, 0.f, 0.f);
        }
    };
    auto stsA = [&](int st) {
        __align__(16) __nv_bfloat16 hi16[16], lo16[16];
        const float* v = (const float*)pa;
#pragma unroll
        for (int i = 0; i < 16; i++) {
            __nv_bfloat16 h = __float2bfloat16(v[i]);
            hi16[i] = h;
            lo16[i] = __float2bfloat16(v[i] - __bfloat162float(h));
        }
        unsigned short* dh = smem + st * STAGEH + lr * SST + lp * 16;
        *(uint4*)(dh)              = *(uint4*)&hi16[0];
        *(uint4*)(dh + 8)          = *(uint4*)&hi16[8];
        *(uint4*)(dh + OFF_AL)     = *(uint4*)&lo16[0];
        *(uint4*)(dh + OFF_AL + 8) = *(uint4*)&lo16[8];
    };
    auto issueB = [&](int c, int st) {
        int k0 = c * 32;
        uint32_t dst = saddr + (uint32_t)(st * STAGEH + lr * SST + lp * 16) * 2;
        const __nv_bfloat16* bh = Bhi + (size_t)(colBase + lr) * Kd + k0 + lp * 16;
        const __nv_bfloat16* bl = Blo + (size_t)(colBase + lr) * Kd + k0 + lp * 16;
        CPA16(dst + OFF_BH * 2, bh);              CPA16(dst + OFF_BH * 2 + 16, bh + 8);
        CPA16(dst + Geo<BN_>::OFF_BL * 2, bl);    CPA16(dst + Geo<BN_>::OFF_BL * 2 + 16, bl + 8);
    };

    // prologue: A0 in smem, A1 in regs, B0/B1 in flight
    ldA(0); stsA(0);
    ldA(1);
    issueB(0, 0); CPC();
    issueB(1, 1); CPC();

    for (int c = 0; c < NC; c++) {
        const int st = c & 1;
        CPW1();
        __syncthreads();
        if (c + 1 < NC) stsA(st ^ 1);
        if (c + 2 < NC) ldA(c + 2);

        const uint32_t s0 = saddr + (uint32_t)(st * STAGEH) * 2;
        compute_kk<BN_>(s0, wmBase, wnBase, lrow, lcol, 0,  acc);
        compute_kk<BN_>(s0, wmBase, wnBase, lrow, lcol, 16, acc);

        __syncthreads();
        if (c + 2 < NC) issueB(c + 2, st);
        CPC();
    }

    // epilogue: relu, split hi/lo -> Y1
#pragma unroll
    for (int mt = 0; mt < 2; mt++) {
#pragma unroll
        for (int hr = 0; hr < 2; hr++) {
            int row = rowBase + wmBase + mt * 16 + hr * 8 + gq;
#pragma unroll
            for (int nt = 0; nt < NT; nt++) {
                int col = colBase + wnBase + nt * 8 + 2 * tq;
                float vx = fmaxf(acc[mt * NT + nt][hr * 2 + 0] + bias[col], 0.f);
                float vy = fmaxf(acc[mt * NT + nt][hr * 2 + 1] + bias[col + 1], 0.f);
                __nv_bfloat16 hx = __float2bfloat16(vx);
                __nv_bfloat16 hy = __float2bfloat16(vy);
                __nv_bfloat16 lx = __float2bfloat16(vx - __bfloat162float(hx));
                __nv_bfloat16 ly = __float2bfloat16(vy - __bfloat162float(hy));
                uint32_t hp  = ((uint32_t)__bfloat16_as_ushort(hy) << 16) | __bfloat16_as_ushort(hx);
                uint32_t lp2 = ((uint32_t)__bfloat16_as_ushort(ly) << 16) | __bfloat16_as_ushort(lx);
                size_t o = (size_t)row * Nd + col;
                *(uint32_t*)&g_Y1hi[o] = hp;
                *(uint32_t*)&g_Y1lo[o] = lp2;
            }
        }
    }
}

// ============ standard grouped GEMM (BN templated) ============
template <bool RELU, bool SCATTER, int BN_>
__global__ __launch_bounds__(256, 2) void k_gemm_mma(
    int lv, int Acode, int Kd, int Nd, size_t woff,
    const float* __restrict__ bias_base, int Ccode, float* __restrict__ outbuf)
{
    const int fid = (lv < L) ? g_tilefid[lv * NTM + blockIdx.x] : g_tilefidG[blockIdx.x];
    if (fid < 0) return;

    constexpr int NT = BN_ / 16;
    constexpr int STAGEH = Geo<BN_>::STAGEH;
    constexpr int STAGES = Geo<BN_>::STAGES;
    const int NC = Kd >> 5;

    const __nv_bfloat16 *Ahi, *Alo;
    if (Acode == 1) { Ahi = g_Y1hi; Alo = g_Y1lo; }
    else            { Ahi = g_Y2hi; Alo = g_Y2lo; }
    const __nv_bfloat16* __restrict__ Bhi = g_Whi + woff + (size_t)fid * Nd * Kd;
    const __nv_bfloat16* __restrict__ Blo = g_Wlo + woff + (size_t)fid * Nd * Kd;
    const float* __restrict__ bias = bias_base + (size_t)fid * Nd;

    const int rowBase = blockIdx.x * 128;
    const int colBase = blockIdx.y * BN_;
    const int tid = threadIdx.x, lane = tid & 31, wid = tid >> 5;
    const int wmBase = (wid & 3) * 32;
    const int wnBase = (wid >> 2) * (BN_ / 2);
    const int gq = lane >> 2, tq = lane & 3;
    const int lrow = lane & 15, lcol = (lane >> 4) << 3;

    extern __shared__ __align__(16) unsigned short smem[];
    const uint32_t saddr = smem_u32(smem);

    float acc[2 * NT][4];
#pragma unroll
    for (int b = 0; b < 2 * NT; b++)
#pragma unroll
        for (int c = 0; c < 4; c++) acc[b][c] = 0.f;

    const int lr = tid >> 1, lp = tid & 1;
    auto issue = [&](int c, int st) {
        int k0 = c * 32;
        uint32_t dst = saddr + (uint32_t)(st * STAGEH + lr * SST + lp * 16) * 2;
        const __nv_bfloat16* ah = Ahi + (size_t)(rowBase + lr) * Kd + k0 + lp * 16;
        const __nv_bfloat16* al = Alo + (size_t)(rowBase + lr) * Kd + k0 + lp * 16;
        CPA16(dst, ah);                     CPA16(dst + 16, ah + 8);
        CPA16(dst + OFF_AL * 2, al);        CPA16(dst + OFF_AL * 2 + 16, al + 8);
        if (BN_ == 128 || lr < BN_) {
            const __nv_bfloat16* bh = Bhi + (size_t)(colBase + lr) * Kd + k0 + lp * 16;
            const __nv_bfloat16* bl = Blo + (size_t)(colBase + lr) * Kd + k0 + lp * 16;
            CPA16(dst + OFF_BH * 2, bh);              CPA16(dst + OFF_BH * 2 + 16, bh + 8);
            CPA16(dst + Geo<BN_>::OFF_BL * 2, bl);    CPA16(dst + Geo<BN_>::OFF_BL * 2 + 16, bl + 8);
        }
    };

    issue(0, 0); CPC();
    issue(1, 1); CPC();

    for (int c = 0; c < NC; c++) {
        if (STAGES == 2) {
            const int st = c & 1;
            CPW1();
            __syncthreads();
            const uint32_t s0 = saddr + (uint32_t)(st * STAGEH) * 2;
            compute_kk<BN_>(s0, wmBase, wnBase, lrow, lcol, 0,  acc);
            compute_kk<BN_>(s0, wmBase, wnBase, lrow, lcol, 16, acc);
            __syncthreads();
            if (c + 2 < NC) issue(c + 2, st);
            CPC();
        } else {
            const int st = c % 3;
            CPW1();
            __syncthreads();
            if (c + 2 < NC) issue(c + 2, (c + 2) % 3);
            CPC();
            const uint32_t s0 = saddr + (uint32_t)(st * STAGEH) * 2;
            compute_kk<BN_>(s0, wmBase, wnBase, lrow, lcol, 0,  acc);
            compute_kk<BN_>(s0, wmBase, wnBase, lrow, lcol, 16, acc);
        }
    }

    // ---- epilogue ----
    const int* perm = (lv < L) ? (g_perm + lv * PADM) : g_permG;

    if (SCATTER) {
        float* Cb;
        if (Ccode == 3)      Cb = g_hA;
        else if (Ccode == 4) Cb = g_hB;
        else                 Cb = outbuf;
#pragma unroll
        for (int mt = 0; mt < 2; mt++) {
#pragma unroll
            for (int hr = 0; hr < 2; hr++) {
                int row = rowBase + wmBase + mt * 16 + hr * 8 + gq;
                int dst = perm[row];
                if (dst < 0) continue;
#pragma unroll
                for (int nt = 0; nt < NT; nt++) {
                    int col = colBase + wnBase + nt * 8 + 2 * tq;
                    float2 v;
                    v.x = acc[mt * NT + nt][hr * 2 + 0] + bias[col];
                    v.y = acc[mt * NT + nt][hr * 2 + 1] + bias[col + 1];
                    if (RELU) { v.x = fmaxf(v.x, 0.f); v.y = fmaxf(v.y, 0.f); }
                    *(float2*)&Cb[(size_t)dst * Nd + col] = v;
                }
            }
        }
    } else {
        __nv_bfloat16* Chi = g_Y2hi;
        __nv_bfloat16* Clo = g_Y2lo;
#pragma unroll
        for (int mt = 0; mt < 2; mt++) {
#pragma unroll
            for (int hr = 0; hr < 2; hr++) {
                int row = rowBase + wmBase + mt * 16 + hr * 8 + gq;
#pragma unroll
                for (int nt = 0; nt < NT; nt++) {
                    int col = colBase + wnBase + nt * 8 + 2 * tq;
                    float vx = acc[mt * NT + nt][hr * 2 + 0] + bias[col];
                    float vy = acc[mt * NT + nt][hr * 2 + 1] + bias[col + 1];
                    if (RELU) { vx = fmaxf(vx, 0.f); vy = fmaxf(vy, 0.f); }
                    __nv_bfloat16 hx = __float2bfloat16(vx);
                    __nv_bfloat16 hy = __float2bfloat16(vy);
                    __nv_bfloat16 lx = __float2bfloat16(vx - __bfloat162float(hx));
                    __nv_bfloat16 ly = __float2bfloat16(vy - __bfloat162float(hy));
                    uint32_t hp  = ((uint32_t)__bfloat16_as_ushort(hy) << 16) | __bfloat16_as_ushort(hx);
                    uint32_t lp2 = ((uint32_t)__bfloat16_as_ushort(ly) << 16) | __bfloat16_as_ushort(lx);
                    size_t o = (size_t)row * Nd + col;
                    *(uint32_t*)&Chi[o] = hp;
                    *(uint32_t*)&Clo[o] = lp2;
                }
            }
        }
    }
}

// ---------------- launch ----------------
extern "C" void kernel_launch(void* const* d_in, const int* in_sizes, int n_in,
                              void* d_out, int out_size)
{
    const int*   leaf_ids = (const int*)d_in[0];
    const int*   left_idx = (const int*)d_in[1];
    const int*   right_idx= (const int*)d_in[2];
    const int*   nf_fid   = (const int*)d_in[3];
    const int*   gt_left  = (const int*)d_in[4];
    const int*   gt_right = (const int*)d_in[5];
    const int*   lf_fid   = (const int*)d_in[6];
    const float* emb      = (const float*)d_in[7];
    const float* W1 = (const float*)d_in[8];
    const float* b1 = (const float*)d_in[9];
    const float* W2 = (const float*)d_in[10];
    const float* b2 = (const float*)d_in[11];
    const float* W3 = (const float*)d_in[12];
    const float* b3 = (const float*)d_in[13];
    const float* Wl1= (const float*)d_in[14];
    const float* bl1= (const float*)d_in[15];
    const float* Wl2= (const float*)d_in[16];
    const float* bl2= (const float*)d_in[17];
    float* out = (float*)d_out;

    cudaFuncSetAttribute(k_gemm_fused,                   cudaFuncAttributeMaxDynamicSharedMemorySize, Geo<128>::SMEM);
    cudaFuncSetAttribute(k_gemm_mma<true,  false, 128>,  cudaFuncAttributeMaxDynamicSharedMemorySize, Geo<128>::SMEM);
    cudaFuncSetAttribute(k_gemm_mma<false, true,  64 >,  cudaFuncAttributeMaxDynamicSharedMemorySize, Geo<64>::SMEM);

    // grouping + weight prep
    k_reset<<<(L * PADM + 255) / 256, 256>>>();
    k_count<<<(L * M + G + 255) / 256, 256>>>(nf_fid, lf_fid);
    k_scan <<<1, 32>>>();
    k_scatter_wconv<<<SCAT_BLOCKS + 3072, 256>>>(nf_fid, lf_fid, W1, W2, W3, Wl1, Wl2);

    int src = 0, dst = 3;   // 0 = emb (level 0), 3/4 = g_hA/g_hB
    for (int l = 0; l < L; l++) {
        dim3 g1(NTM, 4), g2(NTM, 2), g3(NTM, 2);
        k_gemm_fused<<<g1, 256, Geo<128>::SMEM>>>(l, left_idx + l * M, right_idx + l * M,
                                                  src, emb, (l == 0) ? leaf_ids : nullptr,
                                                  OFF_W1, b1);
        k_gemm_mma<true,  false, 128><<<g2, 256, Geo<128>::SMEM>>>(l, 1, 512, 256, OFF_W2, b2, 2, nullptr);
        k_gemm_mma<false, true,  64 ><<<g3, 256, Geo<64>::SMEM >>>(l, 2, 256, 128, OFF_W3, b3, dst, nullptr);
        src = dst; dst = (dst == 3) ? 4 : 3;
    }

    // logic statements on final h (in buffer `src`)
    dim3 gl1(NTG, 4), gl2(NTG, 2);
    k_gemm_fused<<<gl1, 256, Geo<128>::SMEM>>>(L, gt_left, gt_right, src, emb, nullptr,
                                               OFF_WL1, bl1);
    k_gemm_mma<false, true, 64><<<gl2, 256, Geo<64>::SMEM>>>(L, 1, 512, 128, OFF_WL2, bl2, 5, out);
}